// round 7
// baseline (speedup 1.0000x reference)
#include <cuda_runtime.h>
#include <math.h>

// Problem constants (fixed by the dataset)
#define NB 256      // batch (docs)
#define NL 512      // tokens per doc
#define ND 1024     // embedding dim
// emb_table is (V+1, D) = (50001, 1024) float32

// Scratch (device globals — no allocation allowed)
__device__ float g_hpart[NB * 2 * ND];  // per-doc 2-way partial sums of emb rows
__device__ float g_v[NB * ND];          // v[b] = W_b @ mean(emb[b])

// ---------------------------------------------------------------------------
// Pass 1: partial sums of gathered embedding rows.  (EXACT R1 version)
// ---------------------------------------------------------------------------
__global__ void k_hidden(const int* __restrict__ tokens,
                         const float* __restrict__ emb) {
    __shared__ int s_tok[256];
    const int b    = blockIdx.x >> 1;
    const int part = blockIdx.x & 1;
    const int t    = threadIdx.x;

    s_tok[t] = tokens[b * NL + part * 256 + t] + 1;   // +1 per reference lookup
    __syncthreads();

    const float4* emb4 = reinterpret_cast<const float4*>(emb);
    float4 acc = make_float4(0.f, 0.f, 0.f, 0.f);

#pragma unroll 4
    for (int l = 0; l < 256; ++l) {
        const int row = s_tok[l];
        float4 e = __ldg(&emb4[(size_t)row * 256 + t]);
        acc.x += e.x; acc.y += e.y; acc.z += e.z; acc.w += e.w;
    }
    reinterpret_cast<float4*>(g_hpart)[(b * 2 + part) * 256 + t] = acc;
}

// ---------------------------------------------------------------------------
// Small GEMM (R1 scalar): v[b,n] = sum_e hidden[b,e] * W[n,e].
// ---------------------------------------------------------------------------
__global__ void k_v(const float* __restrict__ W) {
    __shared__ float sA[32 * 34];   // [k][m], pad to 34
    __shared__ float sB[32 * 68];   // [k][n], pad to 68

    const int tid = threadIdx.x;
    const int bn0 = blockIdx.x * 64;
    const int bm0 = blockIdx.y * 32;
    const int tx  = tid & 15;
    const int ty  = tid >> 4;
    const int lm  = tid >> 3;
    const int lk  = tid & 7;

    const float4* W4  = reinterpret_cast<const float4*>(W);
    const float4* hp4 = reinterpret_cast<const float4*>(g_hpart);

    float acc[2][4] = {{0.f,0.f,0.f,0.f},{0.f,0.f,0.f,0.f}};

    for (int k0 = 0; k0 < 1024; k0 += 32) {
        {
            const int bb = bm0 + lm;
            float4 h0 = hp4[bb * 512 +       (k0 >> 2) + lk];
            float4 h1 = hp4[bb * 512 + 256 + (k0 >> 2) + lk];
            const float s = 1.0f / 512.0f;
            sA[(lk * 4 + 0) * 34 + lm] = (h0.x + h1.x) * s;
            sA[(lk * 4 + 1) * 34 + lm] = (h0.y + h1.y) * s;
            sA[(lk * 4 + 2) * 34 + lm] = (h0.z + h1.z) * s;
            sA[(lk * 4 + 3) * 34 + lm] = (h0.w + h1.w) * s;
        }
#pragma unroll
        for (int r = 0; r < 2; ++r) {
            const int n = lm + r * 32;
            float4 w = W4[(size_t)(bn0 + n) * 256 + (k0 >> 2) + lk];
            sB[(lk * 4 + 0) * 68 + n] = w.x;
            sB[(lk * 4 + 1) * 68 + n] = w.y;
            sB[(lk * 4 + 2) * 68 + n] = w.z;
            sB[(lk * 4 + 3) * 68 + n] = w.w;
        }
        __syncthreads();

#pragma unroll
        for (int k = 0; k < 32; ++k) {
            float2 a2 = *reinterpret_cast<const float2*>(&sA[k * 34 + ty * 2]);
            float4 b4 = *reinterpret_cast<const float4*>(&sB[k * 68 + tx * 4]);
            acc[0][0] += a2.x * b4.x; acc[0][1] += a2.x * b4.y;
            acc[0][2] += a2.x * b4.z; acc[0][3] += a2.x * b4.w;
            acc[1][0] += a2.y * b4.x; acc[1][1] += a2.y * b4.y;
            acc[1][2] += a2.y * b4.z; acc[1][3] += a2.y * b4.w;
        }
        __syncthreads();
    }

#pragma unroll
    for (int i = 0; i < 2; ++i) {
        const int row = bm0 + ty * 2 + i;
        float4 o = make_float4(acc[i][0], acc[i][1], acc[i][2], acc[i][3]);
        reinterpret_cast<float4*>(g_v)[row * 256 + (bn0 >> 2) + tx] = o;
    }
}

// ---------------------------------------------------------------------------
// Pass 2: split-D warp pairs + software-pipelined token loop (unroll 2,
// register double-buffered embedding rows). 1 CTA/doc, 512 thr = 8 pairs;
// pair p handles tokens p*64..+63, half h owns D-components h*512..+511.
// ---------------------------------------------------------------------------
__global__ void __launch_bounds__(512, 1)
k_ct(const int* __restrict__ tokens, const float* __restrict__ emb,
     float* __restrict__ out) {
    __shared__ int   s_tok[512];
    __shared__ float s_ct[1024];
    __shared__ float s_ex[8][2][2];   // [pair][token parity][half]
    __shared__ float s_m[8];
    __shared__ float s_d[8];

    const int b    = blockIdx.x;
    const int tid  = threadIdx.x;
    const int w    = tid >> 5;
    const int p    = w >> 1;          // pair 0..7
    const int h    = w & 1;           // D-half 0/1
    const int lane = tid & 31;

    s_tok[tid]      = tokens[b * NL + tid] + 1;
    s_ct[tid]       = 0.f;
    s_ct[tid + 512] = 0.f;
    __syncthreads();

    const float4* emb4 = reinterpret_cast<const float4*>(emb);
    const float4* v4   = reinterpret_cast<const float4*>(g_v);
    const float4* base = emb4 + h * 128 + lane;   // half-row base + lane offset

    float4 vr[4];
#pragma unroll
    for (int it = 0; it < 4; ++it) vr[it] = v4[b * 256 + h * 128 + it * 32 + lane];

    float4 nacc[4];
#pragma unroll
    for (int it = 0; it < 4; ++it) nacc[it] = make_float4(0.f, 0.f, 0.f, 0.f);

    float m   = -INFINITY;
    float den = 0.f;

    // Prologue: load tokens j=0 (eA) and j=1 (eB)
    float4 eA[4], eB[4];
    {
        const float4* q0 = base + (size_t)s_tok[p * 64 + 0] * 256;
        const float4* q1 = base + (size_t)s_tok[p * 64 + 1] * 256;
#pragma unroll
        for (int it = 0; it < 4; ++it) eA[it] = q0[it * 32];
#pragma unroll
        for (int it = 0; it < 4; ++it) eB[it] = q1[it * 32];
    }

#define PROCESS(EBUF, PARITY)                                               \
    {                                                                       \
        float s = EBUF[0].x * vr[0].x + EBUF[0].y * vr[0].y                 \
                + EBUF[0].z * vr[0].z + EBUF[0].w * vr[0].w                 \
                + EBUF[1].x * vr[1].x + EBUF[1].y * vr[1].y                 \
                + EBUF[1].z * vr[1].z + EBUF[1].w * vr[1].w                 \
                + EBUF[2].x * vr[2].x + EBUF[2].y * vr[2].y                 \
                + EBUF[2].z * vr[2].z + EBUF[2].w * vr[2].w                 \
                + EBUF[3].x * vr[3].x + EBUF[3].y * vr[3].y                 \
                + EBUF[3].z * vr[3].z + EBUF[3].w * vr[3].w;                \
        _Pragma("unroll")                                                   \
        for (int o = 16; o; o >>= 1) s += __shfl_xor_sync(0xffffffffu, s, o); \
        if (lane == 0) s_ex[p][PARITY][h] = s;                              \
        asm volatile("bar.sync %0, 64;" :: "r"(p + 1) : "memory");          \
        s = s_ex[p][PARITY][0] + s_ex[p][PARITY][1];                        \
        const float m_new = fmaxf(m, s);                                    \
        const float c  = __expf(m - m_new);                                 \
        const float wl = __expf(s - m_new);                                 \
        den = den * c + wl;                                                 \
        if (c != 1.0f) {                                                    \
            _Pragma("unroll")                                               \
            for (int it = 0; it < 4; ++it) {                                \
                nacc[it].x *= c; nacc[it].y *= c;                           \
                nacc[it].z *= c; nacc[it].w *= c;                           \
            }                                                               \
        }                                                                   \
        _Pragma("unroll")                                                   \
        for (int it = 0; it < 4; ++it) {                                    \
            nacc[it].x += wl * EBUF[it].x; nacc[it].y += wl * EBUF[it].y;   \
            nacc[it].z += wl * EBUF[it].z; nacc[it].w += wl * EBUF[it].w;   \
        }                                                                   \
        m = m_new;                                                          \
    }

    for (int j = 0; j < 64; j += 2) {
        // process token j (in eA), then refill eA with token j+2
        PROCESS(eA, 0);
        if (j + 2 < 64) {
            const float4* q = base + (size_t)s_tok[p * 64 + j + 2] * 256;
#pragma unroll
            for (int it = 0; it < 4; ++it) eA[it] = q[it * 32];
        }
        // process token j+1 (in eB), then refill eB with token j+3
        PROCESS(eB, 1);
        if (j + 3 < 64) {
            const float4* q = base + (size_t)s_tok[p * 64 + j + 3] * 256;
#pragma unroll
            for (int it = 0; it < 4; ++it) eB[it] = q[it * 32];
        }
    }
#undef PROCESS

    // per-pair state (identical in both halves of a pair)
    if (h == 0 && lane == 0) { s_m[p] = m; s_d[p] = den; }
    __syncthreads();

    float M = -INFINITY;
#pragma unroll
    for (int i = 0; i < 8; ++i) M = fmaxf(M, s_m[i]);
    float dg = 0.f;
#pragma unroll
    for (int i = 0; i < 8; ++i) dg += s_d[i] * __expf(s_m[i] - M);

    const float sc = __expf(m - M) / dg;
#pragma unroll
    for (int it = 0; it < 4; ++it) {
        const int d0 = h * 512 + it * 128 + lane * 4;
        atomicAdd(&s_ct[d0 + 0], nacc[it].x * sc);
        atomicAdd(&s_ct[d0 + 1], nacc[it].y * sc);
        atomicAdd(&s_ct[d0 + 2], nacc[it].z * sc);
        atomicAdd(&s_ct[d0 + 3], nacc[it].w * sc);
    }
    __syncthreads();

    out[b * ND + tid]       = s_ct[tid];
    out[b * ND + tid + 512] = s_ct[tid + 512];
}

// ---------------------------------------------------------------------------
extern "C" void kernel_launch(void* const* d_in, const int* in_sizes, int n_in,
                              void* d_out, int out_size) {
    const int*   tokens = (const int*)d_in[0];
    // d_in[1] = max_len (scalar, unused — fixed at 512)
    const float* emb    = (const float*)d_in[2];
    const float* W      = (const float*)d_in[3];
    float*       out    = (float*)d_out;

    k_hidden<<<NB * 2, 256>>>(tokens, emb);
    k_v<<<dim3(16, 8), 256>>>(W);
    k_ct<<<NB, 512>>>(tokens, emb, out);
}

// round 8
// speedup vs baseline: 1.0689x; 1.0689x over previous
#include <cuda_runtime.h>
#include <math.h>

// Problem constants (fixed by the dataset)
#define NB 256      // batch (docs)
#define NL 512      // tokens per doc
#define ND 1024     // embedding dim
// emb_table is (V+1, D) = (50001, 1024) float32

// Scratch (device globals — no allocation allowed)
__device__ float g_hpart[NB * 2 * ND];  // per-doc 2-way partial sums of emb rows
__device__ float g_v[NB * ND];          // v[b] = W_b @ mean(emb[b])

// ---------------------------------------------------------------------------
// Pass 1: partial sums of gathered embedding rows.  (EXACT R1 version)
// ---------------------------------------------------------------------------
__global__ void k_hidden(const int* __restrict__ tokens,
                         const float* __restrict__ emb) {
    __shared__ int s_tok[256];
    const int b    = blockIdx.x >> 1;
    const int part = blockIdx.x & 1;
    const int t    = threadIdx.x;

    s_tok[t] = tokens[b * NL + part * 256 + t] + 1;   // +1 per reference lookup
    __syncthreads();

    const float4* emb4 = reinterpret_cast<const float4*>(emb);
    float4 acc = make_float4(0.f, 0.f, 0.f, 0.f);

#pragma unroll 4
    for (int l = 0; l < 256; ++l) {
        const int row = s_tok[l];
        float4 e = __ldg(&emb4[(size_t)row * 256 + t]);
        acc.x += e.x; acc.y += e.y; acc.z += e.z; acc.w += e.w;
    }
    reinterpret_cast<float4*>(g_hpart)[(b * 2 + part) * 256 + t] = acc;
}

// ---------------------------------------------------------------------------
// Small GEMM (R1 scalar): v[b,n] = sum_e hidden[b,e] * W[n,e].
// ---------------------------------------------------------------------------
__global__ void k_v(const float* __restrict__ W) {
    __shared__ float sA[32 * 34];   // [k][m], pad to 34
    __shared__ float sB[32 * 68];   // [k][n], pad to 68

    const int tid = threadIdx.x;
    const int bn0 = blockIdx.x * 64;
    const int bm0 = blockIdx.y * 32;
    const int tx  = tid & 15;
    const int ty  = tid >> 4;
    const int lm  = tid >> 3;
    const int lk  = tid & 7;

    const float4* W4  = reinterpret_cast<const float4*>(W);
    const float4* hp4 = reinterpret_cast<const float4*>(g_hpart);

    float acc[2][4] = {{0.f,0.f,0.f,0.f},{0.f,0.f,0.f,0.f}};

    for (int k0 = 0; k0 < 1024; k0 += 32) {
        {
            const int bb = bm0 + lm;
            float4 h0 = hp4[bb * 512 +       (k0 >> 2) + lk];
            float4 h1 = hp4[bb * 512 + 256 + (k0 >> 2) + lk];
            const float s = 1.0f / 512.0f;
            sA[(lk * 4 + 0) * 34 + lm] = (h0.x + h1.x) * s;
            sA[(lk * 4 + 1) * 34 + lm] = (h0.y + h1.y) * s;
            sA[(lk * 4 + 2) * 34 + lm] = (h0.z + h1.z) * s;
            sA[(lk * 4 + 3) * 34 + lm] = (h0.w + h1.w) * s;
        }
#pragma unroll
        for (int r = 0; r < 2; ++r) {
            const int n = lm + r * 32;
            float4 w = W4[(size_t)(bn0 + n) * 256 + (k0 >> 2) + lk];
            sB[(lk * 4 + 0) * 68 + n] = w.x;
            sB[(lk * 4 + 1) * 68 + n] = w.y;
            sB[(lk * 4 + 2) * 68 + n] = w.z;
            sB[(lk * 4 + 3) * 68 + n] = w.w;
        }
        __syncthreads();

#pragma unroll
        for (int k = 0; k < 32; ++k) {
            float2 a2 = *reinterpret_cast<const float2*>(&sA[k * 34 + ty * 2]);
            float4 b4 = *reinterpret_cast<const float4*>(&sB[k * 68 + tx * 4]);
            acc[0][0] += a2.x * b4.x; acc[0][1] += a2.x * b4.y;
            acc[0][2] += a2.x * b4.z; acc[0][3] += a2.x * b4.w;
            acc[1][0] += a2.y * b4.x; acc[1][1] += a2.y * b4.y;
            acc[1][2] += a2.y * b4.z; acc[1][3] += a2.y * b4.w;
        }
        __syncthreads();
    }

#pragma unroll
    for (int i = 0; i < 2; ++i) {
        const int row = bm0 + ty * 2 + i;
        float4 o = make_float4(acc[i][0], acc[i][1], acc[i][2], acc[i][3]);
        reinterpret_cast<float4*>(g_v)[row * 256 + (bn0 >> 2) + tx] = o;
    }
}

// ---------------------------------------------------------------------------
// Pass 2: 4-way D-split warp quads + 4-token batches.
// 1 CTA/doc, 512 thr = 16 warps = 4 quads. Quad q handles tokens q*128..+127
// in batches of 4; warp part r owns D-quarter r (2 float4 per lane).
// One named barrier (id q+1, 128 thr) per 4 tokens; s_ex double-buffered.
// 2 CTAs/SM -> 256 CTAs in one wave, 32 warps/SM.
// ---------------------------------------------------------------------------
__global__ void __launch_bounds__(512, 2)
k_ct(const int* __restrict__ tokens, const float* __restrict__ emb,
     float* __restrict__ out) {
    __shared__ int   s_tok[512];
    __shared__ float s_ct[1024];
    __shared__ float s_ex[4][2][4][4];   // [quad][parity][g][part]
    __shared__ float s_m[4];
    __shared__ float s_d[4];

    const int b    = blockIdx.x;
    const int tid  = threadIdx.x;
    const int w    = tid >> 5;
    const int q    = w >> 2;          // quad 0..3
    const int r    = w & 3;           // D-quarter 0..3
    const int lane = tid & 31;

    s_tok[tid]      = tokens[b * NL + tid] + 1;
    s_ct[tid]       = 0.f;
    s_ct[tid + 512] = 0.f;
    __syncthreads();

    const float4* emb4 = reinterpret_cast<const float4*>(emb);
    const float4* v4   = reinterpret_cast<const float4*>(g_v);
    const float4* base = emb4 + r * 64 + lane;   // quarter-row base + lane

    // lane owns D-components d = r*256 + it*128 + lane*4 .. +3, it = 0..1
    float4 vr[2];
    vr[0] = v4[b * 256 + r * 64 + lane];
    vr[1] = v4[b * 256 + r * 64 + 32 + lane];

    float4 nacc[2];
    nacc[0] = make_float4(0.f, 0.f, 0.f, 0.f);
    nacc[1] = make_float4(0.f, 0.f, 0.f, 0.f);

    float m   = -INFINITY;
    float den = 0.f;

    for (int j0 = 0; j0 < 128; j0 += 4) {
        const int par = (j0 >> 2) & 1;

        // Load 4 rows (8 independent LDG.128 per lane)
        float4 e[4][2];
#pragma unroll
        for (int g = 0; g < 4; ++g) {
            const float4* p = base + (size_t)s_tok[q * 128 + j0 + g] * 256;
            e[g][0] = p[0];
            e[g][1] = p[32];
        }

        // 4 independent partial dots + shfl reductions (chains overlap)
        float s[4];
#pragma unroll
        for (int g = 0; g < 4; ++g) {
            float t = e[g][0].x * vr[0].x + e[g][0].y * vr[0].y
                    + e[g][0].z * vr[0].z + e[g][0].w * vr[0].w
                    + e[g][1].x * vr[1].x + e[g][1].y * vr[1].y
                    + e[g][1].z * vr[1].z + e[g][1].w * vr[1].w;
#pragma unroll
            for (int o = 16; o; o >>= 1) t += __shfl_xor_sync(0xffffffffu, t, o);
            s[g] = t;
        }

        if (lane == 0) {
#pragma unroll
            for (int g = 0; g < 4; ++g) s_ex[q][par][g][r] = s[g];
        }
        asm volatile("bar.sync %0, 128;" :: "r"(q + 1) : "memory");
#pragma unroll
        for (int g = 0; g < 4; ++g) {
            float4 t4 = *reinterpret_cast<const float4*>(&s_ex[q][par][g][0]);
            s[g] = t4.x + t4.y + t4.z + t4.w;
        }

        // Online softmax over the 4 tokens (short scalar chain)
#pragma unroll
        for (int g = 0; g < 4; ++g) {
            const float m_new = fmaxf(m, s[g]);
            const float c  = __expf(m - m_new);   // 0 on very first token
            const float wl = __expf(s[g] - m_new);
            den = den * c + wl;
            if (c != 1.0f) {
                nacc[0].x *= c; nacc[0].y *= c; nacc[0].z *= c; nacc[0].w *= c;
                nacc[1].x *= c; nacc[1].y *= c; nacc[1].z *= c; nacc[1].w *= c;
            }
            nacc[0].x += wl * e[g][0].x; nacc[0].y += wl * e[g][0].y;
            nacc[0].z += wl * e[g][0].z; nacc[0].w += wl * e[g][0].w;
            nacc[1].x += wl * e[g][1].x; nacc[1].y += wl * e[g][1].y;
            nacc[1].z += wl * e[g][1].z; nacc[1].w += wl * e[g][1].w;
            m = m_new;
        }
    }

    // per-quad state (identical across the 4 parts of a quad)
    if (r == 0 && lane == 0) { s_m[q] = m; s_d[q] = den; }
    __syncthreads();

    float M = -INFINITY;
#pragma unroll
    for (int i = 0; i < 4; ++i) M = fmaxf(M, s_m[i]);
    float dg = 0.f;
#pragma unroll
    for (int i = 0; i < 4; ++i) dg += s_d[i] * __expf(s_m[i] - M);

    const float sc = __expf(m - M) / dg;
#pragma unroll
    for (int it = 0; it < 2; ++it) {
        const int d0 = r * 256 + it * 128 + lane * 4;
        atomicAdd(&s_ct[d0 + 0], nacc[it].x * sc);
        atomicAdd(&s_ct[d0 + 1], nacc[it].y * sc);
        atomicAdd(&s_ct[d0 + 2], nacc[it].z * sc);
        atomicAdd(&s_ct[d0 + 3], nacc[it].w * sc);
    }
    __syncthreads();

    out[b * ND + tid]       = s_ct[tid];
    out[b * ND + tid + 512] = s_ct[tid + 512];
}

// ---------------------------------------------------------------------------
extern "C" void kernel_launch(void* const* d_in, const int* in_sizes, int n_in,
                              void* d_out, int out_size) {
    const int*   tokens = (const int*)d_in[0];
    // d_in[1] = max_len (scalar, unused — fixed at 512)
    const float* emb    = (const float*)d_in[2];
    const float* W      = (const float*)d_in[3];
    float*       out    = (float*)d_out;

    k_hidden<<<NB * 2, 256>>>(tokens, emb);
    k_v<<<dim3(16, 8), 256>>>(W);
    k_ct<<<NB, 512>>>(tokens, emb, out);
}